// round 13
// baseline (speedup 1.0000x reference)
#include <cuda_runtime.h>
#include <math.h>

#define Nn 8
#define Cc 256
#define Ll 512
#define Kk 100
#define ROWS (Nn * Ll)          // 4096
#define INV_TEMP 2.0f           // 1/0.5
#define EPS 1e-8f
#define QSCALE 250.0f           // int8 quant scale for normalized rows
#define DEQ (INV_TEMP / (QSCALE * QSCALE))

// Scratch (no runtime allocation allowed)
__device__ signed char g_z8[ROWS * Cc];  // z transposed + normalized, int8*250 (1MB)
__device__ signed char g_c8[ROWS * Cc];  // c transposed + normalized, int8*250 (1MB)

// ---------------------------------------------------------------------------
// Fused pre-pass v2: norms + transpose + normalize + int8 quantize.
// grid=512: [which(2)][n(8)][ltile16(32)], block=256. 16 loads/thread,
// ~3.5 blocks/SM (2x R12 parallelism). Write phase: 16 lanes per row, rotated
// slab reads (conflict-free: 16w + 17*((i+w)&15) + l distinct mod 32), one
// uint4 store per thread (row's 256 B by 16 lanes).
// ---------------------------------------------------------------------------
__global__ void prep_k(const float* __restrict__ z, const float* __restrict__ c,
                       float* __restrict__ out)
{
    __shared__ float slab[Cc][17];
    __shared__ float part[16][17];
    __shared__ float inv_sh[16];

    int bb    = blockIdx.x;
    int lt    = bb & 31;
    int n     = (bb >> 5) & 7;
    int which = bb >> 8;

    if (bb == 0 && threadIdx.x == 0) out[0] = 0.0f;

    int cols = which ? (Ll + 1) : Ll;
    const float* src = (which ? c : z) + (size_t)n * Cc * cols + (which ? 1 : 0)
                     + lt * 16;

    int tx = threadIdx.x & 15;          // l lane
    int ty = threadIdx.x >> 4;          // c group (16 c's each)

    float acc = 0.f;
#pragma unroll
    for (int i = 0; i < 16; i++) {
        int cc = ty * 16 + i;
        float v = src[(size_t)cc * cols + tx];
        slab[cc][tx] = v;
        acc += v * v;
    }
    part[ty][tx] = acc;
    __syncthreads();

    if (threadIdx.x < 16) {
        float s = 0.f;
#pragma unroll
        for (int k = 0; k < 16; k++) s += part[k][threadIdx.x];
        inv_sh[threadIdx.x] = QSCALE / fmaxf(sqrtf(s), EPS);
    }
    __syncthreads();

    // Write: l = tid>>4 (0..15), w = tid&15 covers c in [16w, 16w+16).
    int l = threadIdx.x >> 4;
    int w = threadIdx.x & 15;
    float iv = inv_sh[l];
    int row = n * Ll + lt * 16 + l;
    signed char* gout = which ? g_c8 : g_z8;

    __align__(16) signed char hh[16];
#pragma unroll
    for (int i = 0; i < 16; i++) {
        int ci = (i + w) & 15;          // conflict-free rotation
        int b = __float2int_rn(slab[16 * w + ci][l] * iv);
        hh[ci] = (signed char)max(-127, min(127, b));
    }
    ((uint4*)(gout + (size_t)row * Cc))[w] = *(const uint4*)hh;
}

// ---------------------------------------------------------------------------
// Main: one block per row, 128 threads = 16 octets (8 lanes). Octet o owns
// dots d = o + 16*it, it=0..6 (d==100 is the positive; it==7 is a dummy).
// Per dot: contiguous 256 B int8 row (lane ol: bytes [16ol,+16), [128+16ol,
// +16)); 8 DP4A/lane; octet sum via ONE REDUX (__reduce_add_sync). Unroll 4
// -> 8 LDG.128 in flight per thread. Indices preloaded + shfl-broadcast.
// ---------------------------------------------------------------------------
__global__ void __launch_bounds__(128, 10)
logits_k(const int* __restrict__ neg_inds, float* __restrict__ out)
{
    __shared__ uint4 c_sh[16];
    __shared__ float logit_sh[Kk + 1];

    int row = blockIdx.x;
    int tid = threadIdx.x;
    int oct = tid >> 3;                 // 0..15
    int ol  = tid & 7;
    int ow8 = ((tid >> 3) & 3) * 8;     // octet base lane within warp
    unsigned maskO = 0xFFu << (tid & 24);

    if (tid < 16)
        c_sh[tid] = ((const uint4*)(g_c8 + (size_t)row * Cc))[tid];

    // lane ol holds the gather index for it = ol (0..6); ol==7 stays = row
    int jreg = row;
    if (ol < 7) {
        int d = oct + 16 * ol;
        if (d < Kk)
            jreg = __ldg(&neg_inds[(size_t)row * Kk + d]);
    }
    __syncthreads();

    uint4 ca = c_sh[ol];
    uint4 cb = c_sh[8 + ol];
    int c0 = (int)ca.x, c1 = (int)ca.y, c2 = (int)ca.z, c3 = (int)ca.w;
    int c4 = (int)cb.x, c5 = (int)cb.y, c6 = (int)cb.z, c7 = (int)cb.w;

#define DOT(pa, pb, sval) do {                                                \
        int _s = 0;                                                           \
        _s = __dp4a((int)pa.x, c0, _s);                                       \
        _s = __dp4a((int)pa.y, c1, _s);                                       \
        _s = __dp4a((int)pa.z, c2, _s);                                       \
        _s = __dp4a((int)pa.w, c3, _s);                                       \
        _s = __dp4a((int)pb.x, c4, _s);                                       \
        _s = __dp4a((int)pb.y, c5, _s);                                       \
        _s = __dp4a((int)pb.z, c6, _s);                                       \
        _s = __dp4a((int)pb.w, c7, _s);                                       \
        sval = _s;                                                            \
    } while (0)

#pragma unroll 1
    for (int p = 0; p < 2; p++) {
        int itb = 4 * p;
        int j0 = __shfl_sync(0xffffffffu, jreg, ow8 + itb + 0);
        int j1 = __shfl_sync(0xffffffffu, jreg, ow8 + itb + 1);
        int j2 = __shfl_sync(0xffffffffu, jreg, ow8 + itb + 2);
        int j3 = __shfl_sync(0xffffffffu, jreg, ow8 + itb + 3);

        const uint4* zr0 = (const uint4*)(g_z8 + (size_t)j0 * Cc);
        const uint4* zr1 = (const uint4*)(g_z8 + (size_t)j1 * Cc);
        const uint4* zr2 = (const uint4*)(g_z8 + (size_t)j2 * Cc);
        const uint4* zr3 = (const uint4*)(g_z8 + (size_t)j3 * Cc);
        uint4 pa0 = zr0[ol], pb0 = zr0[8 + ol];
        uint4 pa1 = zr1[ol], pb1 = zr1[8 + ol];
        uint4 pa2 = zr2[ol], pb2 = zr2[8 + ol];
        uint4 pa3 = zr3[ol], pb3 = zr3[8 + ol];

        int s0, s1, s2, s3;
        DOT(pa0, pb0, s0);
        DOT(pa1, pb1, s1);
        DOT(pa2, pb2, s2);
        DOT(pa3, pb3, s3);

        s0 = __reduce_add_sync(maskO, s0);
        s1 = __reduce_add_sync(maskO, s1);
        s2 = __reduce_add_sync(maskO, s2);
        s3 = __reduce_add_sync(maskO, s3);

        if (ol == 0) {
            int d0 = oct + 16 * (itb + 0);
            int d1 = oct + 16 * (itb + 1);
            int d2 = oct + 16 * (itb + 2);
            int d3 = oct + 16 * (itb + 3);
            if (d0 <= Kk) logit_sh[(d0 == Kk) ? 0 : d0 + 1] = (float)s0 * DEQ;
            if (d1 <= Kk) logit_sh[(d1 == Kk) ? 0 : d1 + 1] = (float)s1 * DEQ;
            if (d2 <= Kk) logit_sh[(d2 == Kk) ? 0 : d2 + 1] = (float)s2 * DEQ;
            if (d3 <= Kk) logit_sh[(d3 == Kk) ? 0 : d3 + 1] = (float)s3 * DEQ;
        }
    }
#undef DOT
    __syncthreads();

    if (tid < 32) {
        int lane = tid;
        float v0 = logit_sh[lane];
        float v1 = (lane + 32 < Kk + 1) ? logit_sh[lane + 32] : -INFINITY;
        float v2 = (lane + 64 < Kk + 1) ? logit_sh[lane + 64] : -INFINITY;
        float v3 = (lane + 96 < Kk + 1) ? logit_sh[lane + 96] : -INFINITY;
        float m = fmaxf(fmaxf(v0, v1), fmaxf(v2, v3));
#pragma unroll
        for (int off = 16; off; off >>= 1)
            m = fmaxf(m, __shfl_xor_sync(0xffffffffu, m, off));
        float e = __expf(v0 - m)
                + ((lane + 32 < Kk + 1) ? __expf(v1 - m) : 0.0f)
                + ((lane + 64 < Kk + 1) ? __expf(v2 - m) : 0.0f)
                + ((lane + 96 < Kk + 1) ? __expf(v3 - m) : 0.0f);
#pragma unroll
        for (int off = 16; off; off >>= 1)
            e += __shfl_xor_sync(0xffffffffu, e, off);
        if (lane == 0) {
            float item = m + logf(e) - logit_sh[0];
            atomicAdd(out, item * (1.0f / (float)ROWS));
        }
    }
}

extern "C" void kernel_launch(void* const* d_in, const int* in_sizes, int n_in,
                              void* d_out, int out_size)
{
    const float* z  = (const float*)d_in[0];   // (8, 256, 512)
    const float* c  = (const float*)d_in[1];   // (8, 256, 513)
    const int* inds = (const int*)d_in[2];     // (8, 512, 100)
    float* out = (float*)d_out;

    prep_k<<<512, 256>>>(z, c, out);
    logits_k<<<ROWS, 128>>>(inds, out);
}

// round 14
// speedup vs baseline: 1.1651x; 1.1651x over previous
#include <cuda_runtime.h>
#include <math.h>

#define Nn 8
#define Cc 256
#define Ll 512
#define Kk 100
#define ROWS (Nn * Ll)          // 4096
#define INV_TEMP 2.0f           // 1/0.5
#define EPS 1e-8f
#define QSCALE 250.0f           // int8 quant scale for normalized rows
#define DEQ (INV_TEMP / (QSCALE * QSCALE))

// Scratch (no runtime allocation allowed)
__device__ signed char g_z8[ROWS * Cc];  // z transposed + normalized, int8*250 (1MB)
__device__ signed char g_c8[ROWS * Cc];  // c transposed + normalized, int8*250 (1MB)

// ---------------------------------------------------------------------------
// Fused pre-pass (R12 version — measured ~5.2us): norms + transpose +
// normalize + int8 quantize. grid=256: [which(2)][n(8)][ltile32(16)], b=256.
// ---------------------------------------------------------------------------
__global__ void prep_k(const float* __restrict__ z, const float* __restrict__ c,
                       float* __restrict__ out)
{
    __shared__ float slab[Cc][33];
    __shared__ float part[8][33];
    __shared__ float inv_sh[32];

    int bb    = blockIdx.x;
    int lt    = bb & 15;
    int n     = (bb >> 4) & 7;
    int which = bb >> 7;

    if (bb == 0 && threadIdx.x == 0) out[0] = 0.0f;

    int cols = which ? (Ll + 1) : Ll;
    const float* src = (which ? c : z) + (size_t)n * Cc * cols + (which ? 1 : 0)
                     + lt * 32;

    int tx = threadIdx.x & 31;          // l lane
    int ty = threadIdx.x >> 5;          // c group

    float acc = 0.f;
#pragma unroll 8
    for (int i = 0; i < 32; i++) {
        int cc = ty * 32 + i;
        float v = src[(size_t)cc * cols + tx];
        slab[cc][tx] = v;
        acc += v * v;
    }
    part[ty][tx] = acc;
    __syncthreads();

    if (threadIdx.x < 32) {
        float s = 0.f;
#pragma unroll
        for (int k = 0; k < 8; k++) s += part[k][tx];
        inv_sh[tx] = QSCALE / fmaxf(sqrtf(s), EPS);
    }
    __syncthreads();

    // Write phase: ty covers 4 l's; lanes sweep c contiguously.
    signed char* gout = which ? g_c8 : g_z8;
#pragma unroll
    for (int i = 0; i < 4; i++) {
        int l   = ty * 4 + i;
        float iv = inv_sh[l];
        int row = n * Ll + lt * 32 + l;
        signed char* dst = gout + (size_t)row * Cc;
#pragma unroll
        for (int ch = 0; ch < 8; ch++) {
            int c0 = ch * 32 + tx;
            int b = __float2int_rn(slab[c0][l] * iv);
            b = max(-127, min(127, b));
            dst[c0] = (signed char)b;
        }
    }
}

// ---------------------------------------------------------------------------
// Main (R12 structure — measured 15.8us — with the octet shuffle reduction
// replaced by a single REDUX.SUM): one block per row, 128 threads = 16
// octets (8 lanes). Octet o owns dots d = o + 16*it, it=0..6 (d==100 is the
// positive). Contiguous 256 B int8 row per dot; 8 DP4A/lane; unroll 2.
// ---------------------------------------------------------------------------
__global__ void logits_k(const int* __restrict__ neg_inds, float* __restrict__ out)
{
    __shared__ uint4 c_sh[16];
    __shared__ float logit_sh[Kk + 1];

    int row = blockIdx.x;
    int tid = threadIdx.x;
    int oct = tid >> 3;                 // 0..15
    int ol  = tid & 7;
    int ow8 = ((tid >> 3) & 3) * 8;     // octet base lane within warp
    unsigned maskO = 0xFFu << (tid & 24);

    if (tid < 16)
        c_sh[tid] = ((const uint4*)(g_c8 + (size_t)row * Cc))[tid];

    // lane ol holds the gather index for it = ol (0..6)
    int jreg = row;
    if (ol < 7) {
        int d = oct + 16 * ol;
        if (d < Kk)
            jreg = __ldg(&neg_inds[(size_t)row * Kk + d]);
    }
    __syncthreads();

    // c bytes [16*ol, +16) and [128+16*ol, +16) — matches z load mapping
    uint4 ca = c_sh[ol];
    uint4 cb = c_sh[8 + ol];
    int c0 = (int)ca.x, c1 = (int)ca.y, c2 = (int)ca.z, c3 = (int)ca.w;
    int c4 = (int)cb.x, c5 = (int)cb.y, c6 = (int)cb.z, c7 = (int)cb.w;

#define DOT(pa, pb, sval) do {                                                \
        int _s = 0;                                                           \
        _s = __dp4a((int)pa.x, c0, _s);                                       \
        _s = __dp4a((int)pa.y, c1, _s);                                       \
        _s = __dp4a((int)pa.z, c2, _s);                                       \
        _s = __dp4a((int)pa.w, c3, _s);                                       \
        _s = __dp4a((int)pb.x, c4, _s);                                       \
        _s = __dp4a((int)pb.y, c5, _s);                                       \
        _s = __dp4a((int)pb.z, c6, _s);                                       \
        _s = __dp4a((int)pb.w, c7, _s);                                       \
        sval = _s;                                                            \
    } while (0)

#pragma unroll 1
    for (int p = 0; p < 4; p++) {
        int it0 = 2 * p, it1 = 2 * p + 1;
        int j0 = __shfl_sync(0xffffffffu, jreg, ow8 + it0);
        int j1 = __shfl_sync(0xffffffffu, jreg, ow8 + it1);

        const uint4* zr0 = (const uint4*)(g_z8 + (size_t)j0 * Cc);
        const uint4* zr1 = (const uint4*)(g_z8 + (size_t)j1 * Cc);
        uint4 pa0 = zr0[ol];        // contiguous 128B per octet
        uint4 pb0 = zr0[8 + ol];    // second 128B line
        uint4 pa1 = zr1[ol];
        uint4 pb1 = zr1[8 + ol];

        int s0, s1;
        DOT(pa0, pb0, s0);
        DOT(pa1, pb1, s1);

        s0 = __reduce_add_sync(maskO, s0);
        s1 = __reduce_add_sync(maskO, s1);

        if (ol == 0) {
            int d0 = oct + 16 * it0;
            int d1 = oct + 16 * it1;
            if (d0 <= Kk) logit_sh[(d0 == Kk) ? 0 : d0 + 1] = (float)s0 * DEQ;
            if (d1 <= Kk) logit_sh[(d1 == Kk) ? 0 : d1 + 1] = (float)s1 * DEQ;
        }
    }
#undef DOT
    __syncthreads();

    if (tid < 32) {
        int lane = tid;
        float v0 = logit_sh[lane];
        float v1 = (lane + 32 < Kk + 1) ? logit_sh[lane + 32] : -INFINITY;
        float v2 = (lane + 64 < Kk + 1) ? logit_sh[lane + 64] : -INFINITY;
        float v3 = (lane + 96 < Kk + 1) ? logit_sh[lane + 96] : -INFINITY;
        float m = fmaxf(fmaxf(v0, v1), fmaxf(v2, v3));
#pragma unroll
        for (int off = 16; off; off >>= 1)
            m = fmaxf(m, __shfl_xor_sync(0xffffffffu, m, off));
        float e = __expf(v0 - m)
                + ((lane + 32 < Kk + 1) ? __expf(v1 - m) : 0.0f)
                + ((lane + 64 < Kk + 1) ? __expf(v2 - m) : 0.0f)
                + ((lane + 96 < Kk + 1) ? __expf(v3 - m) : 0.0f);
#pragma unroll
        for (int off = 16; off; off >>= 1)
            e += __shfl_xor_sync(0xffffffffu, e, off);
        if (lane == 0) {
            float item = m + logf(e) - logit_sh[0];
            atomicAdd(out, item * (1.0f / (float)ROWS));
        }
    }
}

extern "C" void kernel_launch(void* const* d_in, const int* in_sizes, int n_in,
                              void* d_out, int out_size)
{
    const float* z  = (const float*)d_in[0];   // (8, 256, 512)
    const float* c  = (const float*)d_in[1];   // (8, 256, 513)
    const int* inds = (const int*)d_in[2];     // (8, 512, 100)
    float* out = (float*)d_out;

    prep_k<<<256, 256>>>(z, c, out);
    logits_k<<<ROWS, 128>>>(inds, out);
}

// round 15
// speedup vs baseline: 1.4307x; 1.2280x over previous
#include <cuda_runtime.h>
#include <math.h>

#define Nn 8
#define Cc 256
#define Ll 512
#define Kk 100
#define ROWS (Nn * Ll)          // 4096
#define INV_TEMP 2.0f           // 1/0.5
#define EPS 1e-8f
#define QSCALE 250.0f           // int8 quant scale for normalized rows
#define DEQ (INV_TEMP / (QSCALE * QSCALE))

// Scratch (no runtime allocation allowed)
__device__ signed char g_z8[ROWS * Cc];  // z transposed + normalized, int8*250 (1MB)
__device__ signed char g_c8[ROWS * Cc];  // c transposed + normalized, int8*250 (1MB)

// ---------------------------------------------------------------------------
// Fused pre-pass (R12 structure, load loop FULLY unrolled so all 32 LDGs are
// in flight before the STS drain — one DRAM-latency exposure instead of 4).
// grid=256: [which(2)][n(8)][ltile32(16)], block=256.
// ---------------------------------------------------------------------------
__global__ void prep_k(const float* __restrict__ z, const float* __restrict__ c,
                       float* __restrict__ out)
{
    __shared__ float slab[Cc][33];
    __shared__ float part[8][33];
    __shared__ float inv_sh[32];

    int bb    = blockIdx.x;
    int lt    = bb & 15;
    int n     = (bb >> 4) & 7;
    int which = bb >> 7;

    if (bb == 0 && threadIdx.x == 0) out[0] = 0.0f;

    int cols = which ? (Ll + 1) : Ll;
    const float* src = (which ? c : z) + (size_t)n * Cc * cols + (which ? 1 : 0)
                     + lt * 32;

    int tx = threadIdx.x & 31;          // l lane
    int ty = threadIdx.x >> 5;          // c group

    // Full unroll: 32 independent LDGs issued back-to-back (max MLP), then
    // the register->smem/accumulate drain pays DRAM latency once.
    float v[32];
#pragma unroll
    for (int i = 0; i < 32; i++)
        v[i] = src[(size_t)(ty * 32 + i) * cols + tx];

    float acc = 0.f;
#pragma unroll
    for (int i = 0; i < 32; i++) {
        slab[ty * 32 + i][tx] = v[i];
        acc += v[i] * v[i];
    }
    part[ty][tx] = acc;
    __syncthreads();

    if (threadIdx.x < 32) {
        float s = 0.f;
#pragma unroll
        for (int k = 0; k < 8; k++) s += part[k][tx];
        inv_sh[tx] = QSCALE / fmaxf(sqrtf(s), EPS);
    }
    __syncthreads();

    // Write phase: ty covers 4 l's; lanes sweep c contiguously.
    signed char* gout = which ? g_c8 : g_z8;
#pragma unroll
    for (int i = 0; i < 4; i++) {
        int l   = ty * 4 + i;
        float iv = inv_sh[l];
        int row = n * Ll + lt * 32 + l;
        signed char* dst = gout + (size_t)row * Cc;
#pragma unroll
        for (int ch = 0; ch < 8; ch++) {
            int c0 = ch * 32 + tx;
            int b = __float2int_rn(slab[c0][l] * iv);
            b = max(-127, min(127, b));
            dst[c0] = (signed char)b;
        }
    }
}

// ---------------------------------------------------------------------------
// Main (R12 EXACT — measured 15.8us): one block per row, 128 threads = 16
// octets (8 lanes). Octet o owns dots d = o + 16*it, it=0..6 (d==100 is the
// positive). Contiguous 256 B int8 row per dot (lane ol: bytes [16ol,+16),
// [128+16ol,+16)); 8 DP4A/lane; 3-shuffle octet reduce; unroll 2.
// ---------------------------------------------------------------------------
__global__ void logits_k(const int* __restrict__ neg_inds, float* __restrict__ out)
{
    __shared__ uint4 c_sh[16];
    __shared__ float logit_sh[Kk + 1];

    int row = blockIdx.x;
    int tid = threadIdx.x;
    int oct = tid >> 3;                 // 0..15
    int ol  = tid & 7;
    int ow8 = ((tid >> 3) & 3) * 8;     // octet base lane within warp

    if (tid < 16)
        c_sh[tid] = ((const uint4*)(g_c8 + (size_t)row * Cc))[tid];

    // lane ol holds the gather index for it = ol (0..6)
    int jreg = row;
    if (ol < 7) {
        int d = oct + 16 * ol;
        if (d < Kk)
            jreg = __ldg(&neg_inds[(size_t)row * Kk + d]);
    }
    __syncthreads();

    // c bytes [16*ol, +16) and [128+16*ol, +16) — matches z load mapping
    uint4 ca = c_sh[ol];
    uint4 cb = c_sh[8 + ol];
    int c0 = (int)ca.x, c1 = (int)ca.y, c2 = (int)ca.z, c3 = (int)ca.w;
    int c4 = (int)cb.x, c5 = (int)cb.y, c6 = (int)cb.z, c7 = (int)cb.w;

#define DOT(pa, pb, sval) do {                                                \
        int _s = 0;                                                           \
        _s = __dp4a((int)pa.x, c0, _s);                                       \
        _s = __dp4a((int)pa.y, c1, _s);                                       \
        _s = __dp4a((int)pa.z, c2, _s);                                       \
        _s = __dp4a((int)pa.w, c3, _s);                                       \
        _s = __dp4a((int)pb.x, c4, _s);                                       \
        _s = __dp4a((int)pb.y, c5, _s);                                       \
        _s = __dp4a((int)pb.z, c6, _s);                                       \
        _s = __dp4a((int)pb.w, c7, _s);                                       \
        sval = _s;                                                            \
    } while (0)

#pragma unroll 1
    for (int p = 0; p < 4; p++) {
        int it0 = 2 * p, it1 = 2 * p + 1;
        int j0 = __shfl_sync(0xffffffffu, jreg, ow8 + it0);
        int j1 = __shfl_sync(0xffffffffu, jreg, ow8 + it1);

        const uint4* zr0 = (const uint4*)(g_z8 + (size_t)j0 * Cc);
        const uint4* zr1 = (const uint4*)(g_z8 + (size_t)j1 * Cc);
        uint4 pa0 = zr0[ol];        // contiguous 128B per octet
        uint4 pb0 = zr0[8 + ol];    // second 128B line
        uint4 pa1 = zr1[ol];
        uint4 pb1 = zr1[8 + ol];

        int s0, s1;
        DOT(pa0, pb0, s0);
        DOT(pa1, pb1, s1);
#pragma unroll
        for (int off = 4; off; off >>= 1) {
            s0 += __shfl_xor_sync(0xffffffffu, s0, off);
            s1 += __shfl_xor_sync(0xffffffffu, s1, off);
        }
        if (ol == 0) {
            int d0 = oct + 16 * it0;
            int d1 = oct + 16 * it1;
            if (d0 <= Kk) logit_sh[(d0 == Kk) ? 0 : d0 + 1] = (float)s0 * DEQ;
            if (d1 <= Kk) logit_sh[(d1 == Kk) ? 0 : d1 + 1] = (float)s1 * DEQ;
        }
    }
#undef DOT
    __syncthreads();

    if (tid < 32) {
        int lane = tid;
        float v0 = logit_sh[lane];
        float v1 = (lane + 32 < Kk + 1) ? logit_sh[lane + 32] : -INFINITY;
        float v2 = (lane + 64 < Kk + 1) ? logit_sh[lane + 64] : -INFINITY;
        float v3 = (lane + 96 < Kk + 1) ? logit_sh[lane + 96] : -INFINITY;
        float m = fmaxf(fmaxf(v0, v1), fmaxf(v2, v3));
#pragma unroll
        for (int off = 16; off; off >>= 1)
            m = fmaxf(m, __shfl_xor_sync(0xffffffffu, m, off));
        float e = __expf(v0 - m)
                + ((lane + 32 < Kk + 1) ? __expf(v1 - m) : 0.0f)
                + ((lane + 64 < Kk + 1) ? __expf(v2 - m) : 0.0f)
                + ((lane + 96 < Kk + 1) ? __expf(v3 - m) : 0.0f);
#pragma unroll
        for (int off = 16; off; off >>= 1)
            e += __shfl_xor_sync(0xffffffffu, e, off);
        if (lane == 0) {
            float item = m + logf(e) - logit_sh[0];
            atomicAdd(out, item * (1.0f / (float)ROWS));
        }
    }
}

extern "C" void kernel_launch(void* const* d_in, const int* in_sizes, int n_in,
                              void* d_out, int out_size)
{
    const float* z  = (const float*)d_in[0];   // (8, 256, 512)
    const float* c  = (const float*)d_in[1];   // (8, 256, 513)
    const int* inds = (const int*)d_in[2];     // (8, 512, 100)
    float* out = (float*)d_out;

    prep_k<<<256, 256>>>(z, c, out);
    logits_k<<<ROWS, 128>>>(inds, out);
}

// round 16
// speedup vs baseline: 1.4332x; 1.0017x over previous
#include <cuda_runtime.h>
#include <math.h>

#define Nn 8
#define Cc 256
#define Ll 512
#define Kk 100
#define ROWS (Nn * Ll)          // 4096
#define INV_TEMP 2.0f           // 1/0.5
#define EPS 1e-8f
#define QSCALE 250.0f           // int8 quant scale for normalized rows
#define DEQ (INV_TEMP / (QSCALE * QSCALE))

// Scratch (no runtime allocation allowed)
__device__ signed char g_z8[ROWS * Cc];  // z transposed + normalized, int8*250 (1MB)
__device__ signed char g_c8[ROWS * Cc];  // c transposed + normalized, int8*250 (1MB)

// ---------------------------------------------------------------------------
// Fused pre-pass (R15 version — measured ~3.0us): norms + transpose +
// normalize + int8 quantize, load loop fully unrolled (32 LDGs in flight).
// grid=256: [which(2)][n(8)][ltile32(16)], block=256.
// ---------------------------------------------------------------------------
__global__ void prep_k(const float* __restrict__ z, const float* __restrict__ c,
                       float* __restrict__ out)
{
    __shared__ float slab[Cc][33];
    __shared__ float part[8][33];
    __shared__ float inv_sh[32];

    int bb    = blockIdx.x;
    int lt    = bb & 15;
    int n     = (bb >> 4) & 7;
    int which = bb >> 7;

    if (bb == 0 && threadIdx.x == 0) out[0] = 0.0f;

    int cols = which ? (Ll + 1) : Ll;
    const float* src = (which ? c : z) + (size_t)n * Cc * cols + (which ? 1 : 0)
                     + lt * 32;

    int tx = threadIdx.x & 31;          // l lane
    int ty = threadIdx.x >> 5;          // c group

    float v[32];
#pragma unroll
    for (int i = 0; i < 32; i++)
        v[i] = src[(size_t)(ty * 32 + i) * cols + tx];

    float acc = 0.f;
#pragma unroll
    for (int i = 0; i < 32; i++) {
        slab[ty * 32 + i][tx] = v[i];
        acc += v[i] * v[i];
    }
    part[ty][tx] = acc;
    __syncthreads();

    if (threadIdx.x < 32) {
        float s = 0.f;
#pragma unroll
        for (int k = 0; k < 8; k++) s += part[k][tx];
        inv_sh[tx] = QSCALE / fmaxf(sqrtf(s), EPS);
    }
    __syncthreads();

    signed char* gout = which ? g_c8 : g_z8;
#pragma unroll
    for (int i = 0; i < 4; i++) {
        int l   = ty * 4 + i;
        float iv = inv_sh[l];
        int row = n * Ll + lt * 32 + l;
        signed char* dst = gout + (size_t)row * Cc;
#pragma unroll
        for (int ch = 0; ch < 8; ch++) {
            int c0 = ch * 32 + tx;
            int b = __float2int_rn(slab[c0][l] * iv);
            b = max(-127, min(127, b));
            dst[c0] = (signed char)b;
        }
    }
}

// ---------------------------------------------------------------------------
// Main: one block per row, 128 threads = 16 octets (8 lanes). Octet o owns
// dots d = o + 16*it, it=0..6 (d==100 is the positive). Contiguous 256 B
// int8 row per dot; 8 DP4A/lane in TWO 4-deep chains. NO in-loop reduction:
// each lane stores its raw partial to part_sh[d][ol] (banks 8*oct+ol, all 32
// distinct per warp). Epilogue: thread d sums its 8 partials (2x LDS.128,
// exact int math), then warp 0 does the logsumexp.
// ---------------------------------------------------------------------------
__global__ void logits_k(const int* __restrict__ neg_inds, float* __restrict__ out)
{
    __shared__ uint4 c_sh[16];
    __shared__ int part_sh[112][8];     // d = oct + 16*it <= 111
    __shared__ float logit_sh[Kk + 1];

    int row = blockIdx.x;
    int tid = threadIdx.x;
    int oct = tid >> 3;                 // 0..15
    int ol  = tid & 7;
    int ow8 = ((tid >> 3) & 3) * 8;     // octet base lane within warp

    if (tid < 16)
        c_sh[tid] = ((const uint4*)(g_c8 + (size_t)row * Cc))[tid];

    // lane ol holds the gather index for it = ol (0..6)
    int jreg = row;
    if (ol < 7) {
        int d = oct + 16 * ol;
        if (d < Kk)
            jreg = __ldg(&neg_inds[(size_t)row * Kk + d]);
    }
    __syncthreads();

    // c bytes [16*ol, +16) and [128+16*ol, +16) — matches z load mapping
    uint4 ca = c_sh[ol];
    uint4 cb = c_sh[8 + ol];
    int c0 = (int)ca.x, c1 = (int)ca.y, c2 = (int)ca.z, c3 = (int)ca.w;
    int c4 = (int)cb.x, c5 = (int)cb.y, c6 = (int)cb.z, c7 = (int)cb.w;

#define DOT(pa, pb, sval) do {                                                \
        int _a = 0, _b = 0;                                                   \
        _a = __dp4a((int)pa.x, c0, _a);                                       \
        _b = __dp4a((int)pa.y, c1, _b);                                       \
        _a = __dp4a((int)pa.z, c2, _a);                                       \
        _b = __dp4a((int)pa.w, c3, _b);                                       \
        _a = __dp4a((int)pb.x, c4, _a);                                       \
        _b = __dp4a((int)pb.y, c5, _b);                                       \
        _a = __dp4a((int)pb.z, c6, _a);                                       \
        _b = __dp4a((int)pb.w, c7, _b);                                       \
        sval = _a + _b;                                                       \
    } while (0)

#pragma unroll 1
    for (int p = 0; p < 4; p++) {
        int it0 = 2 * p, it1 = 2 * p + 1;
        int j0 = __shfl_sync(0xffffffffu, jreg, ow8 + it0);
        int j1 = __shfl_sync(0xffffffffu, jreg, ow8 + it1);

        const uint4* zr0 = (const uint4*)(g_z8 + (size_t)j0 * Cc);
        const uint4* zr1 = (const uint4*)(g_z8 + (size_t)j1 * Cc);
        uint4 pa0 = zr0[ol];        // contiguous 128B per octet
        uint4 pb0 = zr0[8 + ol];    // second 128B line
        uint4 pa1 = zr1[ol];
        uint4 pb1 = zr1[8 + ol];

        int s0, s1;
        DOT(pa0, pb0, s0);
        DOT(pa1, pb1, s1);

        // unconditional: d <= 111 < 112 rows; only d <= 100 is read later
        part_sh[oct + 16 * it0][ol] = s0;
        part_sh[oct + 16 * it1][ol] = s1;
    }
#undef DOT
    __syncthreads();

    if (tid <= Kk) {
        int4 a = *(const int4*)&part_sh[tid][0];
        int4 b = *(const int4*)&part_sh[tid][4];
        int s = (a.x + a.y) + (a.z + a.w) + (b.x + b.y) + (b.z + b.w);
        logit_sh[(tid == Kk) ? 0 : tid + 1] = (float)s * DEQ;
    }
    __syncthreads();

    if (tid < 32) {
        int lane = tid;
        float v0 = logit_sh[lane];
        float v1 = (lane + 32 < Kk + 1) ? logit_sh[lane + 32] : -INFINITY;
        float v2 = (lane + 64 < Kk + 1) ? logit_sh[lane + 64] : -INFINITY;
        float v3 = (lane + 96 < Kk + 1) ? logit_sh[lane + 96] : -INFINITY;
        float m = fmaxf(fmaxf(v0, v1), fmaxf(v2, v3));
#pragma unroll
        for (int off = 16; off; off >>= 1)
            m = fmaxf(m, __shfl_xor_sync(0xffffffffu, m, off));
        float e = __expf(v0 - m)
                + ((lane + 32 < Kk + 1) ? __expf(v1 - m) : 0.0f)
                + ((lane + 64 < Kk + 1) ? __expf(v2 - m) : 0.0f)
                + ((lane + 96 < Kk + 1) ? __expf(v3 - m) : 0.0f);
#pragma unroll
        for (int off = 16; off; off >>= 1)
            e += __shfl_xor_sync(0xffffffffu, e, off);
        if (lane == 0) {
            float item = m + logf(e) - logit_sh[0];
            atomicAdd(out, item * (1.0f / (float)ROWS));
        }
    }
}

extern "C" void kernel_launch(void* const* d_in, const int* in_sizes, int n_in,
                              void* d_out, int out_size)
{
    const float* z  = (const float*)d_in[0];   // (8, 256, 512)
    const float* c  = (const float*)d_in[1];   // (8, 256, 513)
    const int* inds = (const int*)d_in[2];     // (8, 512, 100)
    float* out = (float*)d_out;

    prep_k<<<256, 256>>>(z, c, out);
    logits_k<<<ROWS, 128>>>(inds, out);
}